// round 12
// baseline (speedup 1.0000x reference)
#include <cuda_runtime.h>
#include <cuda_fp16.h>
#include <math.h>
#include <stdint.h>

// ---------------------------------------------------------------------------
// GCN node classifier.
//   CSR by destination (+implicit self loop), dinv = rsqrt(deg+1).
//   layer: G = rowscale(dinv)*(X @ W)  [stored FP16];
//          Y[v] = relu(dinv[v]*(G[v]+sum G[u]) + b)  [FP32]
//   head:  OUT = Y @ Wl + bl  [FP32]
// FP16 G halves the agg gather traffic (agg was at ~85% of the L2 roofline).
// Accumulation is FP32 throughout; only G is quantized (~1.4e-4 RMS/layer).
// ---------------------------------------------------------------------------

#define N_NODES 40000
#define C_FEAT  128
#define N_EDGES 640000

__device__ __half d_g[(size_t)N_NODES * C_FEAT];   // GEMM output, fp16
__device__ float  d_y[(size_t)N_NODES * C_FEAT];   // aggregated, fp32
__device__ int    d_cnt[N_NODES];      // zero-init; scan re-zeroes after use
__device__ int    d_off[N_NODES + 1];
__device__ int    d_cursor[N_NODES];
__device__ int    d_adj[N_EDGES];
__device__ float  d_dinv[N_NODES];

// ---------------------------------------------------------------------------
__global__ void hist_kernel(const int* __restrict__ ei, int E) {
    int i = blockIdx.x * blockDim.x + threadIdx.x;
    if (i * 4 < E) {
        int4 v = *(const int4*)&ei[E + i * 4];
        atomicAdd(&d_cnt[v.x], 1);
        atomicAdd(&d_cnt[v.y], 1);
        atomicAdd(&d_cnt[v.z], 1);
        atomicAdd(&d_cnt[v.w], 1);
    }
}

// Single 1024-thread block; 40 coalesced tiles, register carry.
__global__ void scan_kernel() {
    __shared__ int wred[33];
    const int NT = (N_NODES + 1023) / 1024;   // 40 tiles
    int tid = threadIdx.x, lane = tid & 31, wid = tid >> 5;
    int carry = 0;

    for (int t = 0; t < NT; t++) {
        int i = t * 1024 + tid;
        int c = (i < N_NODES) ? d_cnt[i] : 0;
        int v = c;
#pragma unroll
        for (int d = 1; d < 32; d <<= 1) {
            int u = __shfl_up_sync(0xffffffffu, v, d);
            if (lane >= d) v += u;
        }
        __syncthreads();
        if (lane == 31) wred[wid] = v;
        __syncthreads();
        if (wid == 0) {
            int wv = wred[lane];
            int iv = wv;
#pragma unroll
            for (int d = 1; d < 32; d <<= 1) {
                int u = __shfl_up_sync(0xffffffffu, iv, d);
                if (lane >= d) iv += u;
            }
            wred[lane] = iv - wv;
            if (lane == 31) wred[32] = iv;
        }
        __syncthreads();
        int pos = carry + wred[wid] + (v - c);
        if (i < N_NODES) {
            d_off[i] = pos;
            d_cursor[i] = pos;
            d_dinv[i] = rsqrtf((float)(c + 1));
            d_cnt[i] = 0;                 // restore invariant for next replay
        }
        carry += wred[32];
    }
    if (tid == 0) d_off[N_NODES] = carry;
}

__global__ void scatter_kernel(const int* __restrict__ ei, int E) {
    int i = blockIdx.x * blockDim.x + threadIdx.x;
    if (i * 4 < E) {
        int4 r = *(const int4*)&ei[i * 4];       // sources
        int4 c = *(const int4*)&ei[E + i * 4];   // targets
        d_adj[atomicAdd(&d_cursor[c.x], 1)] = r.x;
        d_adj[atomicAdd(&d_cursor[c.y], 1)] = r.y;
        d_adj[atomicAdd(&d_cursor[c.z], 1)] = r.z;
        d_adj[atomicAdd(&d_cursor[c.w], 1)] = r.w;
    }
}

// ---------------------------------------------------------------------------
// tf32 tensor-core GEMM, cp.async 2-stage pipeline.
// C = A[M,128] @ B[128,BN].  CTA: 64 x BN, 8 warps (2x4), warp 32 x BN/4.
// c_sel=1: store fp16 to d_g.  c_sel=0: store fp32 to Cext.
// ---------------------------------------------------------------------------
__device__ __forceinline__ uint32_t f2tf(float f) {
    uint32_t r;
    asm("cvt.rna.tf32.f32 %0, %1;" : "=r"(r) : "f"(f));
    return r;
}

__device__ __forceinline__ void cp16(uint32_t saddr, const void* gptr) {
    asm volatile("cp.async.ca.shared.global [%0], [%1], 16;\n"
                 :: "r"(saddr), "l"(gptr));
}

template <int BN>
__global__ void __launch_bounds__(256, 3)
gemm_tf32_kernel(const float* __restrict__ Aext,
                 const float* __restrict__ B,
                 const float* __restrict__ bias,
                 float* __restrict__ Cext,
                 int a_sel, int c_sel, int use_rowscale) {
    constexpr int BM = 64, KC = 16, NKC = C_FEAT / KC;   // 8 chunks
    constexpr int AP = 20;
    constexpr int NP = BN + 8;
    constexpr int WN = BN / 4;
    constexpr int MF = 2;
    constexpr int NF = WN / 8;
    constexpr int BV = KC * BN / 4;

    __shared__ float As[2][BM * AP];
    __shared__ float Bs[2][KC * NP];

    const float* A = (a_sel == 0) ? Aext : (const float*)d_y;

    int tid = threadIdx.x;
    int lane = tid & 31;
    int wid = tid >> 5;
    int warp_m = wid & 1;
    int warp_n = wid >> 1;
    int qid = lane >> 2;
    int qt = lane & 3;
    int row0 = blockIdx.x * BM;

    uint32_t a_smem[2], b_smem[2];
#pragma unroll
    for (int s = 0; s < 2; s++) {
        a_smem[s] = (uint32_t)__cvta_generic_to_shared(&As[s][0]);
        b_smem[s] = (uint32_t)__cvta_generic_to_shared(&Bs[s][0]);
    }

    auto load_chunk = [&](int kc, int st) {
        int k0 = kc * KC;
        {   // A: 256 float4s, one pass
            int r = tid >> 2, vv = tid & 3;
            int gr = row0 + r; if (gr >= N_NODES) gr = N_NODES - 1;
            cp16(a_smem[st] + (r * AP + vv * 4) * 4,
                 &A[(size_t)gr * C_FEAT + k0 + vv * 4]);
        }
#pragma unroll
        for (int i = 0; i < BV / 256; i++) {
            int idx = tid + i * 256;
            int r = idx / (BN / 4), vv = idx % (BN / 4);
            cp16(b_smem[st] + (r * NP + vv * 4) * 4,
                 &B[(size_t)(k0 + r) * BN + vv * 4]);
        }
        asm volatile("cp.async.commit_group;" ::: "memory");
    };

    float acc[MF][NF][4];
#pragma unroll
    for (int i = 0; i < MF; i++)
#pragma unroll
        for (int j = 0; j < NF; j++)
#pragma unroll
            for (int k = 0; k < 4; k++) acc[i][j][k] = 0.f;

    load_chunk(0, 0);

    for (int kc = 0; kc < NKC; kc++) {
        int st = kc & 1;
        if (kc + 1 < NKC) {
            load_chunk(kc + 1, st ^ 1);
            asm volatile("cp.async.wait_group 1;" ::: "memory");
        } else {
            asm volatile("cp.async.wait_group 0;" ::: "memory");
        }
        __syncthreads();

        const float* __restrict__ Asb = As[st];
        const float* __restrict__ Bsb = Bs[st];
#pragma unroll
        for (int k8 = 0; k8 < KC / 8; k8++) {
            int kb = k8 * 8;
            uint32_t af[MF][4];
#pragma unroll
            for (int im = 0; im < MF; im++) {
                int m0 = warp_m * 32 + im * 16 + qid;
                af[im][0] = f2tf(Asb[m0 * AP + kb + qt]);
                af[im][1] = f2tf(Asb[(m0 + 8) * AP + kb + qt]);
                af[im][2] = f2tf(Asb[m0 * AP + kb + qt + 4]);
                af[im][3] = f2tf(Asb[(m0 + 8) * AP + kb + qt + 4]);
            }
            uint32_t bf[NF][2];
#pragma unroll
            for (int jn = 0; jn < NF; jn++) {
                int n0 = warp_n * WN + jn * 8 + qid;
                bf[jn][0] = f2tf(Bsb[(kb + qt) * NP + n0]);
                bf[jn][1] = f2tf(Bsb[(kb + qt + 4) * NP + n0]);
            }
#pragma unroll
            for (int im = 0; im < MF; im++)
#pragma unroll
                for (int jn = 0; jn < NF; jn++) {
                    asm volatile(
                        "mma.sync.aligned.m16n8k8.row.col.f32.tf32.tf32.f32 "
                        "{%0,%1,%2,%3}, {%4,%5,%6,%7}, {%8,%9}, {%0,%1,%2,%3};\n"
                        : "+f"(acc[im][jn][0]), "+f"(acc[im][jn][1]),
                          "+f"(acc[im][jn][2]), "+f"(acc[im][jn][3])
                        : "r"(af[im][0]), "r"(af[im][1]), "r"(af[im][2]), "r"(af[im][3]),
                          "r"(bf[jn][0]), "r"(bf[jn][1]));
                }
        }
        __syncthreads();
    }

    __half* Ch = (__half*)d_g;
#pragma unroll
    for (int im = 0; im < MF; im++) {
        int ra = row0 + warp_m * 32 + im * 16 + qid;
        int rb = ra + 8;
        float sa = 1.f, sb = 1.f;
        if (use_rowscale) {
            if (ra < N_NODES) sa = d_dinv[ra];
            if (rb < N_NODES) sb = d_dinv[rb];
        }
#pragma unroll
        for (int jn = 0; jn < NF; jn++) {
            int col = warp_n * WN + jn * 8 + qt * 2;
            float bx = 0.f, by = 0.f;
            if (bias) { bx = bias[col]; by = bias[col + 1]; }
            float oax = fmaf(acc[im][jn][0], sa, bx), oay = fmaf(acc[im][jn][1], sa, by);
            float obx = fmaf(acc[im][jn][2], sb, bx), oby = fmaf(acc[im][jn][3], sb, by);
            if (c_sel) {   // fp16 store to d_g
                if (ra < N_NODES)
                    *(__half2*)&Ch[(size_t)ra * BN + col] = __floats2half2_rn(oax, oay);
                if (rb < N_NODES)
                    *(__half2*)&Ch[(size_t)rb * BN + col] = __floats2half2_rn(obx, oby);
            } else {       // fp32 store to external out
                if (ra < N_NODES)
                    *(float2*)&Cext[(size_t)ra * BN + col] = make_float2(oax, oay);
                if (rb < N_NODES)
                    *(float2*)&Cext[(size_t)rb * BN + col] = make_float2(obx, oby);
            }
        }
    }
}

// ---------------------------------------------------------------------------
// Aggregation: one warp per node, fp16 gathers (8B/lane), fp32 accumulate.
// 4 independent accumulator sets keep 4 gathers in flight.
// ---------------------------------------------------------------------------
__device__ __forceinline__ void acc4(float4& a, uint2 v) {
    __half2 h0 = *(__half2*)&v.x, h1 = *(__half2*)&v.y;
    float2 f0 = __half22float2(h0), f1 = __half22float2(h1);
    a.x += f0.x; a.y += f0.y; a.z += f1.x; a.w += f1.y;
}

__global__ void agg_kernel(const float* __restrict__ bias) {
    int gw = (blockIdx.x * blockDim.x + threadIdx.x) >> 5;
    if (gw >= N_NODES) return;
    int lane = threadIdx.x & 31;
    int c = lane << 2;
    const __half* __restrict__ g = (const __half*)d_g;

    float4 a0 = make_float4(0.f, 0.f, 0.f, 0.f);
    float4 a1 = a0, a2 = a0, a3 = a0;
    acc4(a0, *(const uint2*)&g[(size_t)gw * C_FEAT + c]);  // self loop

    int s = d_off[gw], e = d_off[gw + 1];
    for (int base = s; base < e; base += 32) {
        int m = e - base; if (m > 32) m = 32;
        int myu = (lane < m) ? d_adj[base + lane] : 0;
        int j = 0;
        for (; j + 4 <= m; j += 4) {
            int u0 = __shfl_sync(0xffffffffu, myu, j);
            int u1 = __shfl_sync(0xffffffffu, myu, j + 1);
            int u2 = __shfl_sync(0xffffffffu, myu, j + 2);
            int u3 = __shfl_sync(0xffffffffu, myu, j + 3);
            uint2 t0 = *(const uint2*)&g[(size_t)u0 * C_FEAT + c];
            uint2 t1 = *(const uint2*)&g[(size_t)u1 * C_FEAT + c];
            uint2 t2 = *(const uint2*)&g[(size_t)u2 * C_FEAT + c];
            uint2 t3 = *(const uint2*)&g[(size_t)u3 * C_FEAT + c];
            acc4(a0, t0); acc4(a1, t1); acc4(a2, t2); acc4(a3, t3);
        }
        for (; j < m; j++) {
            int u = __shfl_sync(0xffffffffu, myu, j);
            acc4(a0, *(const uint2*)&g[(size_t)u * C_FEAT + c]);
        }
    }
    float4 acc = make_float4(a0.x + a1.x + a2.x + a3.x,
                             a0.y + a1.y + a2.y + a3.y,
                             a0.z + a1.z + a2.z + a3.z,
                             a0.w + a1.w + a2.w + a3.w);
    float dv = d_dinv[gw];
    float4 bb = *(const float4*)&bias[c];
    float4 o;
    o.x = fmaxf(fmaf(acc.x, dv, bb.x), 0.f);
    o.y = fmaxf(fmaf(acc.y, dv, bb.y), 0.f);
    o.z = fmaxf(fmaf(acc.z, dv, bb.z), 0.f);
    o.w = fmaxf(fmaf(acc.w, dv, bb.w), 0.f);
    *(float4*)&d_y[(size_t)gw * C_FEAT + c] = o;
}

// ---------------------------------------------------------------------------
extern "C" void kernel_launch(void* const* d_in, const int* in_sizes, int n_in,
                              void* d_out, int out_size) {
    const float* x  = (const float*)d_in[0];
    const int*   ei = (const int*)d_in[1];     // int32
    const float* W1 = (const float*)d_in[2];
    const float* b1 = (const float*)d_in[3];
    const float* W2 = (const float*)d_in[4];
    const float* b2 = (const float*)d_in[5];
    const float* Wl = (const float*)d_in[6];
    const float* bl = (const float*)d_in[7];
    float* out = (float*)d_out;

    int E = in_sizes[1] / 2;   // 640000

    const int gemm_grid = (N_NODES + 63) / 64;          // 625
    const int agg_grid  = (N_NODES * 32 + 255) / 256;   // 5000

    // CSR build
    hist_kernel<<<(E / 4 + 255) / 256, 256>>>(ei, E);        // 0
    scan_kernel<<<1, 1024>>>();                              // 1
    scatter_kernel<<<(E / 4 + 255) / 256, 256>>>(ei, E);     // 2

    // Layer 1 (launch 3 = gemm1 -> ncu slot)
    gemm_tf32_kernel<128><<<gemm_grid, 256>>>(x, W1, nullptr, nullptr, 0, 1, 1);
    agg_kernel<<<agg_grid, 256>>>(b1);                       // 4
    // Layer 2
    gemm_tf32_kernel<128><<<gemm_grid, 256>>>(nullptr, W2, nullptr, nullptr, 1, 1, 1);
    agg_kernel<<<agg_grid, 256>>>(b2);                       // 6
    // Head
    gemm_tf32_kernel<64><<<gemm_grid, 256>>>(nullptr, Wl, bl, out, 1, 0, 0);
}

// round 13
// speedup vs baseline: 1.1505x; 1.1505x over previous
#include <cuda_runtime.h>
#include <cuda_fp16.h>
#include <math.h>
#include <stdint.h>

// ---------------------------------------------------------------------------
// GCN node classifier.
//   CSR by destination (+implicit self loop), dinv = rsqrt(deg+1).
//   layer: G = rowscale(dinv)*(X @ W)  [stored BF16 pairs];
//          Y[v] = relu(dinv[v]*(G[v]+sum G[u]) + b)  [FP32]
//   head:  OUT = Y @ Wl + bl  [FP32]
// BF16 G halves agg gather traffic; unpack is pure ALU (shift/mask), unlike
// fp16 whose F2F.F32.F16 on the XU pipe caused the R12 regression.
// ---------------------------------------------------------------------------

#define N_NODES 40000
#define C_FEAT  128
#define N_EDGES 640000

__device__ uint32_t d_g[(size_t)N_NODES * C_FEAT / 2];  // bf16x2 pairs
__device__ float    d_y[(size_t)N_NODES * C_FEAT];      // fp32
__device__ int      d_cnt[N_NODES];    // zero-init; scan re-zeroes after use
__device__ int      d_off[N_NODES + 1];
__device__ int      d_cursor[N_NODES];
__device__ int      d_adj[N_EDGES];
__device__ float    d_dinv[N_NODES];

// ---------------------------------------------------------------------------
__global__ void hist_kernel(const int* __restrict__ ei, int E) {
    int i = blockIdx.x * blockDim.x + threadIdx.x;
    if (i * 4 < E) {
        int4 v = *(const int4*)&ei[E + i * 4];
        atomicAdd(&d_cnt[v.x], 1);
        atomicAdd(&d_cnt[v.y], 1);
        atomicAdd(&d_cnt[v.z], 1);
        atomicAdd(&d_cnt[v.w], 1);
    }
}

// Single 1024-thread block; 40 coalesced tiles, register carry.
__global__ void scan_kernel() {
    __shared__ int wred[33];
    const int NT = (N_NODES + 1023) / 1024;   // 40 tiles
    int tid = threadIdx.x, lane = tid & 31, wid = tid >> 5;
    int carry = 0;

    for (int t = 0; t < NT; t++) {
        int i = t * 1024 + tid;
        int c = (i < N_NODES) ? d_cnt[i] : 0;
        int v = c;
#pragma unroll
        for (int d = 1; d < 32; d <<= 1) {
            int u = __shfl_up_sync(0xffffffffu, v, d);
            if (lane >= d) v += u;
        }
        __syncthreads();
        if (lane == 31) wred[wid] = v;
        __syncthreads();
        if (wid == 0) {
            int wv = wred[lane];
            int iv = wv;
#pragma unroll
            for (int d = 1; d < 32; d <<= 1) {
                int u = __shfl_up_sync(0xffffffffu, iv, d);
                if (lane >= d) iv += u;
            }
            wred[lane] = iv - wv;
            if (lane == 31) wred[32] = iv;
        }
        __syncthreads();
        int pos = carry + wred[wid] + (v - c);
        if (i < N_NODES) {
            d_off[i] = pos;
            d_cursor[i] = pos;
            d_dinv[i] = rsqrtf((float)(c + 1));
            d_cnt[i] = 0;                 // restore invariant for next replay
        }
        carry += wred[32];
    }
    if (tid == 0) d_off[N_NODES] = carry;
}

__global__ void scatter_kernel(const int* __restrict__ ei, int E) {
    int i = blockIdx.x * blockDim.x + threadIdx.x;
    if (i * 4 < E) {
        int4 r = *(const int4*)&ei[i * 4];       // sources
        int4 c = *(const int4*)&ei[E + i * 4];   // targets
        d_adj[atomicAdd(&d_cursor[c.x], 1)] = r.x;
        d_adj[atomicAdd(&d_cursor[c.y], 1)] = r.y;
        d_adj[atomicAdd(&d_cursor[c.z], 1)] = r.z;
        d_adj[atomicAdd(&d_cursor[c.w], 1)] = r.w;
    }
}

// ---------------------------------------------------------------------------
// bf16 pack/unpack helpers (ALU-only unpack).
// ---------------------------------------------------------------------------
__device__ __forceinline__ uint32_t pack_bf2(float lo, float hi) {
    uint32_t r;
    asm("cvt.rn.bf16x2.f32 %0, %1, %2;" : "=r"(r) : "f"(hi), "f"(lo));
    return r;   // low half = lo, high half = hi
}

__device__ __forceinline__ void accb(float4& a, uint2 v) {
    a.x += __uint_as_float(v.x << 16);
    a.y += __uint_as_float(v.x & 0xFFFF0000u);
    a.z += __uint_as_float(v.y << 16);
    a.w += __uint_as_float(v.y & 0xFFFF0000u);
}

// ---------------------------------------------------------------------------
// tf32 tensor-core GEMM, cp.async 2-stage pipeline.
// C = A[M,128] @ B[128,BN].  CTA: 64 x BN, 8 warps (2x4), warp 32 x BN/4.
// c_sel=1: store bf16x2 to d_g.  c_sel=0: store fp32 to Cext.
// ---------------------------------------------------------------------------
__device__ __forceinline__ uint32_t f2tf(float f) {
    uint32_t r;
    asm("cvt.rna.tf32.f32 %0, %1;" : "=r"(r) : "f"(f));
    return r;
}

__device__ __forceinline__ void cp16(uint32_t saddr, const void* gptr) {
    asm volatile("cp.async.ca.shared.global [%0], [%1], 16;\n"
                 :: "r"(saddr), "l"(gptr));
}

template <int BN>
__global__ void __launch_bounds__(256, 3)
gemm_tf32_kernel(const float* __restrict__ Aext,
                 const float* __restrict__ B,
                 const float* __restrict__ bias,
                 float* __restrict__ Cext,
                 int a_sel, int c_sel, int use_rowscale) {
    constexpr int BM = 64, KC = 16, NKC = C_FEAT / KC;   // 8 chunks
    constexpr int AP = 20;
    constexpr int NP = BN + 8;
    constexpr int WN = BN / 4;
    constexpr int MF = 2;
    constexpr int NF = WN / 8;
    constexpr int BV = KC * BN / 4;

    __shared__ float As[2][BM * AP];
    __shared__ float Bs[2][KC * NP];

    const float* A = (a_sel == 0) ? Aext : (const float*)d_y;

    int tid = threadIdx.x;
    int lane = tid & 31;
    int wid = tid >> 5;
    int warp_m = wid & 1;
    int warp_n = wid >> 1;
    int qid = lane >> 2;
    int qt = lane & 3;
    int row0 = blockIdx.x * BM;

    uint32_t a_smem[2], b_smem[2];
#pragma unroll
    for (int s = 0; s < 2; s++) {
        a_smem[s] = (uint32_t)__cvta_generic_to_shared(&As[s][0]);
        b_smem[s] = (uint32_t)__cvta_generic_to_shared(&Bs[s][0]);
    }

    auto load_chunk = [&](int kc, int st) {
        int k0 = kc * KC;
        {   // A: 256 float4s, one pass
            int r = tid >> 2, vv = tid & 3;
            int gr = row0 + r; if (gr >= N_NODES) gr = N_NODES - 1;
            cp16(a_smem[st] + (r * AP + vv * 4) * 4,
                 &A[(size_t)gr * C_FEAT + k0 + vv * 4]);
        }
#pragma unroll
        for (int i = 0; i < BV / 256; i++) {
            int idx = tid + i * 256;
            int r = idx / (BN / 4), vv = idx % (BN / 4);
            cp16(b_smem[st] + (r * NP + vv * 4) * 4,
                 &B[(size_t)(k0 + r) * BN + vv * 4]);
        }
        asm volatile("cp.async.commit_group;" ::: "memory");
    };

    float acc[MF][NF][4];
#pragma unroll
    for (int i = 0; i < MF; i++)
#pragma unroll
        for (int j = 0; j < NF; j++)
#pragma unroll
            for (int k = 0; k < 4; k++) acc[i][j][k] = 0.f;

    load_chunk(0, 0);

    for (int kc = 0; kc < NKC; kc++) {
        int st = kc & 1;
        if (kc + 1 < NKC) {
            load_chunk(kc + 1, st ^ 1);
            asm volatile("cp.async.wait_group 1;" ::: "memory");
        } else {
            asm volatile("cp.async.wait_group 0;" ::: "memory");
        }
        __syncthreads();

        const float* __restrict__ Asb = As[st];
        const float* __restrict__ Bsb = Bs[st];
#pragma unroll
        for (int k8 = 0; k8 < KC / 8; k8++) {
            int kb = k8 * 8;
            uint32_t af[MF][4];
#pragma unroll
            for (int im = 0; im < MF; im++) {
                int m0 = warp_m * 32 + im * 16 + qid;
                af[im][0] = f2tf(Asb[m0 * AP + kb + qt]);
                af[im][1] = f2tf(Asb[(m0 + 8) * AP + kb + qt]);
                af[im][2] = f2tf(Asb[m0 * AP + kb + qt + 4]);
                af[im][3] = f2tf(Asb[(m0 + 8) * AP + kb + qt + 4]);
            }
            uint32_t bf[NF][2];
#pragma unroll
            for (int jn = 0; jn < NF; jn++) {
                int n0 = warp_n * WN + jn * 8 + qid;
                bf[jn][0] = f2tf(Bsb[(kb + qt) * NP + n0]);
                bf[jn][1] = f2tf(Bsb[(kb + qt + 4) * NP + n0]);
            }
#pragma unroll
            for (int im = 0; im < MF; im++)
#pragma unroll
                for (int jn = 0; jn < NF; jn++) {
                    asm volatile(
                        "mma.sync.aligned.m16n8k8.row.col.f32.tf32.tf32.f32 "
                        "{%0,%1,%2,%3}, {%4,%5,%6,%7}, {%8,%9}, {%0,%1,%2,%3};\n"
                        : "+f"(acc[im][jn][0]), "+f"(acc[im][jn][1]),
                          "+f"(acc[im][jn][2]), "+f"(acc[im][jn][3])
                        : "r"(af[im][0]), "r"(af[im][1]), "r"(af[im][2]), "r"(af[im][3]),
                          "r"(bf[jn][0]), "r"(bf[jn][1]));
                }
        }
        __syncthreads();
    }

#pragma unroll
    for (int im = 0; im < MF; im++) {
        int ra = row0 + warp_m * 32 + im * 16 + qid;
        int rb = ra + 8;
        float sa = 1.f, sb = 1.f;
        if (use_rowscale) {
            if (ra < N_NODES) sa = d_dinv[ra];
            if (rb < N_NODES) sb = d_dinv[rb];
        }
#pragma unroll
        for (int jn = 0; jn < NF; jn++) {
            int col = warp_n * WN + jn * 8 + qt * 2;
            float bx = 0.f, by = 0.f;
            if (bias) { bx = bias[col]; by = bias[col + 1]; }
            float oax = fmaf(acc[im][jn][0], sa, bx), oay = fmaf(acc[im][jn][1], sa, by);
            float obx = fmaf(acc[im][jn][2], sb, bx), oby = fmaf(acc[im][jn][3], sb, by);
            if (c_sel) {   // bf16x2 store to d_g
                if (ra < N_NODES)
                    d_g[(size_t)ra * (C_FEAT / 2) + (col >> 1)] = pack_bf2(oax, oay);
                if (rb < N_NODES)
                    d_g[(size_t)rb * (C_FEAT / 2) + (col >> 1)] = pack_bf2(obx, oby);
            } else {       // fp32 store to external out
                if (ra < N_NODES)
                    *(float2*)&Cext[(size_t)ra * BN + col] = make_float2(oax, oay);
                if (rb < N_NODES)
                    *(float2*)&Cext[(size_t)rb * BN + col] = make_float2(obx, oby);
            }
        }
    }
}

// ---------------------------------------------------------------------------
// Aggregation: one warp per node, bf16x2 gathers (8B/lane), fp32 accumulate.
// Unpack is shift/mask on the ALU pipe (no XU F2F). 4 independent acc sets.
// ---------------------------------------------------------------------------
__global__ void agg_kernel(const float* __restrict__ bias) {
    int gw = (blockIdx.x * blockDim.x + threadIdx.x) >> 5;
    if (gw >= N_NODES) return;
    int lane = threadIdx.x & 31;
    int cw = lane << 1;                    // word index within 64-word row
    const uint32_t* __restrict__ g = (const uint32_t*)d_g;

    float4 a0 = make_float4(0.f, 0.f, 0.f, 0.f);
    float4 a1 = a0, a2 = a0, a3 = a0;
    accb(a0, *(const uint2*)&g[(size_t)gw * (C_FEAT / 2) + cw]);  // self loop

    int s = d_off[gw], e = d_off[gw + 1];
    for (int base = s; base < e; base += 32) {
        int m = e - base; if (m > 32) m = 32;
        int myu = (lane < m) ? d_adj[base + lane] : 0;
        int j = 0;
        for (; j + 4 <= m; j += 4) {
            int u0 = __shfl_sync(0xffffffffu, myu, j);
            int u1 = __shfl_sync(0xffffffffu, myu, j + 1);
            int u2 = __shfl_sync(0xffffffffu, myu, j + 2);
            int u3 = __shfl_sync(0xffffffffu, myu, j + 3);
            uint2 t0 = *(const uint2*)&g[(size_t)u0 * (C_FEAT / 2) + cw];
            uint2 t1 = *(const uint2*)&g[(size_t)u1 * (C_FEAT / 2) + cw];
            uint2 t2 = *(const uint2*)&g[(size_t)u2 * (C_FEAT / 2) + cw];
            uint2 t3 = *(const uint2*)&g[(size_t)u3 * (C_FEAT / 2) + cw];
            accb(a0, t0); accb(a1, t1); accb(a2, t2); accb(a3, t3);
        }
        for (; j < m; j++) {
            int u = __shfl_sync(0xffffffffu, myu, j);
            accb(a0, *(const uint2*)&g[(size_t)u * (C_FEAT / 2) + cw]);
        }
    }
    float4 acc = make_float4(a0.x + a1.x + a2.x + a3.x,
                             a0.y + a1.y + a2.y + a3.y,
                             a0.z + a1.z + a2.z + a3.z,
                             a0.w + a1.w + a2.w + a3.w);
    int c = lane << 2;
    float dv = d_dinv[gw];
    float4 bb = *(const float4*)&bias[c];
    float4 o;
    o.x = fmaxf(fmaf(acc.x, dv, bb.x), 0.f);
    o.y = fmaxf(fmaf(acc.y, dv, bb.y), 0.f);
    o.z = fmaxf(fmaf(acc.z, dv, bb.z), 0.f);
    o.w = fmaxf(fmaf(acc.w, dv, bb.w), 0.f);
    *(float4*)&d_y[(size_t)gw * C_FEAT + c] = o;
}

// ---------------------------------------------------------------------------
extern "C" void kernel_launch(void* const* d_in, const int* in_sizes, int n_in,
                              void* d_out, int out_size) {
    const float* x  = (const float*)d_in[0];
    const int*   ei = (const int*)d_in[1];     // int32
    const float* W1 = (const float*)d_in[2];
    const float* b1 = (const float*)d_in[3];
    const float* W2 = (const float*)d_in[4];
    const float* b2 = (const float*)d_in[5];
    const float* Wl = (const float*)d_in[6];
    const float* bl = (const float*)d_in[7];
    float* out = (float*)d_out;

    int E = in_sizes[1] / 2;   // 640000

    const int gemm_grid = (N_NODES + 63) / 64;          // 625
    const int agg_grid  = (N_NODES * 32 + 255) / 256;   // 5000

    // CSR build
    hist_kernel<<<(E / 4 + 255) / 256, 256>>>(ei, E);        // 0
    scan_kernel<<<1, 1024>>>();                              // 1
    scatter_kernel<<<(E / 4 + 255) / 256, 256>>>(ei, E);     // 2

    // Layer 1 (launch 3 = gemm1 -> ncu slot)
    gemm_tf32_kernel<128><<<gemm_grid, 256>>>(x, W1, nullptr, nullptr, 0, 1, 1);
    agg_kernel<<<agg_grid, 256>>>(b1);                       // 4
    // Layer 2
    gemm_tf32_kernel<128><<<gemm_grid, 256>>>(nullptr, W2, nullptr, nullptr, 1, 1, 1);
    agg_kernel<<<agg_grid, 256>>>(b2);                       // 6
    // Head
    gemm_tf32_kernel<64><<<gemm_grid, 256>>>(nullptr, Wl, bl, out, 1, 0, 0);
}

// round 15
// speedup vs baseline: 1.1829x; 1.0282x over previous
#include <cuda_runtime.h>
#include <cuda_fp16.h>
#include <math.h>
#include <stdint.h>

// ---------------------------------------------------------------------------
// GCN node classifier.
//   CSR by destination (+implicit self loop), dinv = rsqrt(deg+1).
//   layer: G = rowscale(dinv)*(X @ W)  [BF16 pairs];
//          Y[v] = relu(dinv[v]*(G[v]+sum G[u]) + b)  [FP32]
//   head:  OUT = Y @ Wl + bl  [FP32]
// R15: gemm1 overlaps ONLY scatter (gemm1 needs d_dinv from scan — the R14
// race). Order: hist, scan, fork{gemm1 || scatter}, join, agg1, ...
// ---------------------------------------------------------------------------

#define N_NODES 40000
#define C_FEAT  128
#define N_EDGES 640000

__device__ uint32_t d_g[(size_t)N_NODES * C_FEAT / 2];  // bf16x2 pairs
__device__ float    d_y[(size_t)N_NODES * C_FEAT];      // fp32
__device__ int      d_cnt[N_NODES];    // zero-init; scan re-zeroes after use
__device__ int      d_off[N_NODES + 1];
__device__ int      d_cursor[N_NODES];
__device__ int      d_adj[N_EDGES];
__device__ float    d_dinv[N_NODES];

// ---------------------------------------------------------------------------
__global__ void hist_kernel(const int* __restrict__ ei, int E) {
    int i = blockIdx.x * blockDim.x + threadIdx.x;
    if (i * 4 < E) {
        int4 v = *(const int4*)&ei[E + i * 4];
        atomicAdd(&d_cnt[v.x], 1);
        atomicAdd(&d_cnt[v.y], 1);
        atomicAdd(&d_cnt[v.z], 1);
        atomicAdd(&d_cnt[v.w], 1);
    }
}

// Single 1024-thread block; 40 coalesced tiles, register carry.
__global__ void scan_kernel() {
    __shared__ int wred[33];
    const int NT = (N_NODES + 1023) / 1024;   // 40 tiles
    int tid = threadIdx.x, lane = tid & 31, wid = tid >> 5;
    int carry = 0;

    for (int t = 0; t < NT; t++) {
        int i = t * 1024 + tid;
        int c = (i < N_NODES) ? d_cnt[i] : 0;
        int v = c;
#pragma unroll
        for (int d = 1; d < 32; d <<= 1) {
            int u = __shfl_up_sync(0xffffffffu, v, d);
            if (lane >= d) v += u;
        }
        __syncthreads();
        if (lane == 31) wred[wid] = v;
        __syncthreads();
        if (wid == 0) {
            int wv = wred[lane];
            int iv = wv;
#pragma unroll
            for (int d = 1; d < 32; d <<= 1) {
                int u = __shfl_up_sync(0xffffffffu, iv, d);
                if (lane >= d) iv += u;
            }
            wred[lane] = iv - wv;
            if (lane == 31) wred[32] = iv;
        }
        __syncthreads();
        int pos = carry + wred[wid] + (v - c);
        if (i < N_NODES) {
            d_off[i] = pos;
            d_cursor[i] = pos;
            d_dinv[i] = rsqrtf((float)(c + 1));
            d_cnt[i] = 0;                 // restore invariant for next replay
        }
        carry += wred[32];
    }
    if (tid == 0) d_off[N_NODES] = carry;
}

__global__ void scatter_kernel(const int* __restrict__ ei, int E) {
    int i = blockIdx.x * blockDim.x + threadIdx.x;
    if (i * 4 < E) {
        int4 r = *(const int4*)&ei[i * 4];       // sources
        int4 c = *(const int4*)&ei[E + i * 4];   // targets
        d_adj[atomicAdd(&d_cursor[c.x], 1)] = r.x;
        d_adj[atomicAdd(&d_cursor[c.y], 1)] = r.y;
        d_adj[atomicAdd(&d_cursor[c.z], 1)] = r.z;
        d_adj[atomicAdd(&d_cursor[c.w], 1)] = r.w;
    }
}

// ---------------------------------------------------------------------------
// bf16 pack/unpack helpers (ALU-only unpack).
// ---------------------------------------------------------------------------
__device__ __forceinline__ uint32_t pack_bf2(float lo, float hi) {
    uint32_t r;
    asm("cvt.rn.bf16x2.f32 %0, %1, %2;" : "=r"(r) : "f"(hi), "f"(lo));
    return r;
}

__device__ __forceinline__ void accb(float4& a, uint2 v) {
    a.x += __uint_as_float(v.x << 16);
    a.y += __uint_as_float(v.x & 0xFFFF0000u);
    a.z += __uint_as_float(v.y << 16);
    a.w += __uint_as_float(v.y & 0xFFFF0000u);
}

// ---------------------------------------------------------------------------
// tf32 tensor-core GEMM, cp.async 2-stage pipeline.
// C = A[M,128] @ B[128,BN].  CTA: 64 x BN, 8 warps (2x4), warp 32 x BN/4.
// c_sel=1: store bf16x2 to d_g.  c_sel=0: store fp32 to Cext.
// ---------------------------------------------------------------------------
__device__ __forceinline__ uint32_t f2tf(float f) {
    uint32_t r;
    asm("cvt.rna.tf32.f32 %0, %1;" : "=r"(r) : "f"(f));
    return r;
}

__device__ __forceinline__ void cp16(uint32_t saddr, const void* gptr) {
    asm volatile("cp.async.ca.shared.global [%0], [%1], 16;\n"
                 :: "r"(saddr), "l"(gptr));
}

template <int BN>
__global__ void __launch_bounds__(256, 3)
gemm_tf32_kernel(const float* __restrict__ Aext,
                 const float* __restrict__ B,
                 const float* __restrict__ bias,
                 float* __restrict__ Cext,
                 int a_sel, int c_sel, int use_rowscale) {
    constexpr int BM = 64, KC = 16, NKC = C_FEAT / KC;   // 8 chunks
    constexpr int AP = 20;
    constexpr int NP = BN + 8;
    constexpr int WN = BN / 4;
    constexpr int MF = 2;
    constexpr int NF = WN / 8;
    constexpr int BV = KC * BN / 4;

    __shared__ float As[2][BM * AP];
    __shared__ float Bs[2][KC * NP];

    const float* A = (a_sel == 0) ? Aext : (const float*)d_y;

    int tid = threadIdx.x;
    int lane = tid & 31;
    int wid = tid >> 5;
    int warp_m = wid & 1;
    int warp_n = wid >> 1;
    int qid = lane >> 2;
    int qt = lane & 3;
    int row0 = blockIdx.x * BM;

    uint32_t a_smem[2], b_smem[2];
#pragma unroll
    for (int s = 0; s < 2; s++) {
        a_smem[s] = (uint32_t)__cvta_generic_to_shared(&As[s][0]);
        b_smem[s] = (uint32_t)__cvta_generic_to_shared(&Bs[s][0]);
    }

    auto load_chunk = [&](int kc, int st) {
        int k0 = kc * KC;
        {
            int r = tid >> 2, vv = tid & 3;
            int gr = row0 + r; if (gr >= N_NODES) gr = N_NODES - 1;
            cp16(a_smem[st] + (r * AP + vv * 4) * 4,
                 &A[(size_t)gr * C_FEAT + k0 + vv * 4]);
        }
#pragma unroll
        for (int i = 0; i < BV / 256; i++) {
            int idx = tid + i * 256;
            int r = idx / (BN / 4), vv = idx % (BN / 4);
            cp16(b_smem[st] + (r * NP + vv * 4) * 4,
                 &B[(size_t)(k0 + r) * BN + vv * 4]);
        }
        asm volatile("cp.async.commit_group;" ::: "memory");
    };

    float acc[MF][NF][4];
#pragma unroll
    for (int i = 0; i < MF; i++)
#pragma unroll
        for (int j = 0; j < NF; j++)
#pragma unroll
            for (int k = 0; k < 4; k++) acc[i][j][k] = 0.f;

    load_chunk(0, 0);

    for (int kc = 0; kc < NKC; kc++) {
        int st = kc & 1;
        if (kc + 1 < NKC) {
            load_chunk(kc + 1, st ^ 1);
            asm volatile("cp.async.wait_group 1;" ::: "memory");
        } else {
            asm volatile("cp.async.wait_group 0;" ::: "memory");
        }
        __syncthreads();

        const float* __restrict__ Asb = As[st];
        const float* __restrict__ Bsb = Bs[st];
#pragma unroll
        for (int k8 = 0; k8 < KC / 8; k8++) {
            int kb = k8 * 8;
            uint32_t af[MF][4];
#pragma unroll
            for (int im = 0; im < MF; im++) {
                int m0 = warp_m * 32 + im * 16 + qid;
                af[im][0] = f2tf(Asb[m0 * AP + kb + qt]);
                af[im][1] = f2tf(Asb[(m0 + 8) * AP + kb + qt]);
                af[im][2] = f2tf(Asb[m0 * AP + kb + qt + 4]);
                af[im][3] = f2tf(Asb[(m0 + 8) * AP + kb + qt + 4]);
            }
            uint32_t bf[NF][2];
#pragma unroll
            for (int jn = 0; jn < NF; jn++) {
                int n0 = warp_n * WN + jn * 8 + qid;
                bf[jn][0] = f2tf(Bsb[(kb + qt) * NP + n0]);
                bf[jn][1] = f2tf(Bsb[(kb + qt + 4) * NP + n0]);
            }
#pragma unroll
            for (int im = 0; im < MF; im++)
#pragma unroll
                for (int jn = 0; jn < NF; jn++) {
                    asm volatile(
                        "mma.sync.aligned.m16n8k8.row.col.f32.tf32.tf32.f32 "
                        "{%0,%1,%2,%3}, {%4,%5,%6,%7}, {%8,%9}, {%0,%1,%2,%3};\n"
                        : "+f"(acc[im][jn][0]), "+f"(acc[im][jn][1]),
                          "+f"(acc[im][jn][2]), "+f"(acc[im][jn][3])
                        : "r"(af[im][0]), "r"(af[im][1]), "r"(af[im][2]), "r"(af[im][3]),
                          "r"(bf[jn][0]), "r"(bf[jn][1]));
                }
        }
        __syncthreads();
    }

#pragma unroll
    for (int im = 0; im < MF; im++) {
        int ra = row0 + warp_m * 32 + im * 16 + qid;
        int rb = ra + 8;
        float sa = 1.f, sb = 1.f;
        if (use_rowscale) {
            if (ra < N_NODES) sa = d_dinv[ra];
            if (rb < N_NODES) sb = d_dinv[rb];
        }
#pragma unroll
        for (int jn = 0; jn < NF; jn++) {
            int col = warp_n * WN + jn * 8 + qt * 2;
            float bx = 0.f, by = 0.f;
            if (bias) { bx = bias[col]; by = bias[col + 1]; }
            float oax = fmaf(acc[im][jn][0], sa, bx), oay = fmaf(acc[im][jn][1], sa, by);
            float obx = fmaf(acc[im][jn][2], sb, bx), oby = fmaf(acc[im][jn][3], sb, by);
            if (c_sel) {
                if (ra < N_NODES)
                    d_g[(size_t)ra * (C_FEAT / 2) + (col >> 1)] = pack_bf2(oax, oay);
                if (rb < N_NODES)
                    d_g[(size_t)rb * (C_FEAT / 2) + (col >> 1)] = pack_bf2(obx, oby);
            } else {
                if (ra < N_NODES)
                    *(float2*)&Cext[(size_t)ra * BN + col] = make_float2(oax, oay);
                if (rb < N_NODES)
                    *(float2*)&Cext[(size_t)rb * BN + col] = make_float2(obx, oby);
            }
        }
    }
}

// ---------------------------------------------------------------------------
// Aggregation: one warp per node, bf16x2 gathers (8B/lane), fp32 accumulate.
// ---------------------------------------------------------------------------
__global__ void agg_kernel(const float* __restrict__ bias) {
    int gw = (blockIdx.x * blockDim.x + threadIdx.x) >> 5;
    if (gw >= N_NODES) return;
    int lane = threadIdx.x & 31;
    int cw = lane << 1;
    const uint32_t* __restrict__ g = (const uint32_t*)d_g;

    float4 a0 = make_float4(0.f, 0.f, 0.f, 0.f);
    float4 a1 = a0, a2 = a0, a3 = a0;
    accb(a0, *(const uint2*)&g[(size_t)gw * (C_FEAT / 2) + cw]);  // self loop

    int s = d_off[gw], e = d_off[gw + 1];
    for (int base = s; base < e; base += 32) {
        int m = e - base; if (m > 32) m = 32;
        int myu = (lane < m) ? d_adj[base + lane] : 0;
        int j = 0;
        for (; j + 4 <= m; j += 4) {
            int u0 = __shfl_sync(0xffffffffu, myu, j);
            int u1 = __shfl_sync(0xffffffffu, myu, j + 1);
            int u2 = __shfl_sync(0xffffffffu, myu, j + 2);
            int u3 = __shfl_sync(0xffffffffu, myu, j + 3);
            uint2 t0 = *(const uint2*)&g[(size_t)u0 * (C_FEAT / 2) + cw];
            uint2 t1 = *(const uint2*)&g[(size_t)u1 * (C_FEAT / 2) + cw];
            uint2 t2 = *(const uint2*)&g[(size_t)u2 * (C_FEAT / 2) + cw];
            uint2 t3 = *(const uint2*)&g[(size_t)u3 * (C_FEAT / 2) + cw];
            accb(a0, t0); accb(a1, t1); accb(a2, t2); accb(a3, t3);
        }
        for (; j < m; j++) {
            int u = __shfl_sync(0xffffffffu, myu, j);
            accb(a0, *(const uint2*)&g[(size_t)u * (C_FEAT / 2) + cw]);
        }
    }
    float4 acc = make_float4(a0.x + a1.x + a2.x + a3.x,
                             a0.y + a1.y + a2.y + a3.y,
                             a0.z + a1.z + a2.z + a3.z,
                             a0.w + a1.w + a2.w + a3.w);
    int c = lane << 2;
    float dv = d_dinv[gw];
    float4 bb = *(const float4*)&bias[c];
    float4 o;
    o.x = fmaxf(fmaf(acc.x, dv, bb.x), 0.f);
    o.y = fmaxf(fmaf(acc.y, dv, bb.y), 0.f);
    o.z = fmaxf(fmaf(acc.z, dv, bb.z), 0.f);
    o.w = fmaxf(fmaf(acc.w, dv, bb.w), 0.f);
    *(float4*)&d_y[(size_t)gw * C_FEAT + c] = o;
}

// ---------------------------------------------------------------------------
extern "C" void kernel_launch(void* const* d_in, const int* in_sizes, int n_in,
                              void* d_out, int out_size) {
    const float* x  = (const float*)d_in[0];
    const int*   ei = (const int*)d_in[1];     // int32
    const float* W1 = (const float*)d_in[2];
    const float* b1 = (const float*)d_in[3];
    const float* W2 = (const float*)d_in[4];
    const float* b2 = (const float*)d_in[5];
    const float* Wl = (const float*)d_in[6];
    const float* bl = (const float*)d_in[7];
    float* out = (float*)d_out;

    int E = in_sizes[1] / 2;   // 640000

    static cudaStream_t s2 = []() {
        cudaStream_t s; cudaStreamCreateWithFlags(&s, cudaStreamNonBlocking); return s;
    }();
    static cudaEvent_t evF = []() {
        cudaEvent_t e; cudaEventCreateWithFlags(&e, cudaEventDisableTiming); return e;
    }();
    static cudaEvent_t evJ = []() {
        cudaEvent_t e; cudaEventCreateWithFlags(&e, cudaEventDisableTiming); return e;
    }();

    const int gemm_grid = (N_NODES + 63) / 64;          // 625
    const int agg_grid  = (N_NODES * 32 + 255) / 256;   // 5000

    // hist + scan first: gemm1's rowscale needs d_dinv (R14 race fix).
    hist_kernel<<<(E / 4 + 255) / 256, 256>>>(ei, E);
    scan_kernel<<<1, 1024>>>();

    // Fork: gemm1 (reads x, W1, d_dinv) || scatter (writes d_adj/d_cursor).
    cudaEventRecord(evF, 0);
    cudaStreamWaitEvent(s2, evF, 0);
    gemm_tf32_kernel<128><<<gemm_grid, 256, 0, s2>>>(x, W1, nullptr, nullptr, 0, 1, 1);
    cudaEventRecord(evJ, s2);

    scatter_kernel<<<(E / 4 + 255) / 256, 256>>>(ei, E);

    // Join: agg1 needs both gemm1 (d_g) and the CSR (d_adj).
    cudaStreamWaitEvent(0, evJ, 0);
    agg_kernel<<<agg_grid, 256>>>(b1);
    // Layer 2
    gemm_tf32_kernel<128><<<gemm_grid, 256>>>(nullptr, W2, nullptr, nullptr, 1, 1, 1);
    agg_kernel<<<agg_grid, 256>>>(b2);
    // Head
    gemm_tf32_kernel<64><<<gemm_grid, 256>>>(nullptr, Wl, bl, out, 1, 0, 0);
}

// round 16
// speedup vs baseline: 1.2167x; 1.0286x over previous
#include <cuda_runtime.h>
#include <cuda_fp16.h>
#include <math.h>
#include <stdint.h>

// ---------------------------------------------------------------------------
// GCN node classifier.
//   CSR by destination (+implicit self loop), dinv = rsqrt(deg+1).
//   layer: G = rowscale(dinv)*(X @ W)  [BF16 pairs];
//          Y[v] = relu(dinv[v]*(G[v]+sum G[u]) + b)  [FP32]
//   head:  OUT = Y @ Wl + bl  [FP32]
// R16: split-pipelining. GEMM row r needs only y[r]; agg needs ALL rows of
// the preceding GEMM. So gemm2a(rows<S) runs concurrent with agg1b(nodes>=S),
// and head_a concurrent with agg2b. gemm2 writes d_g2 (separate buffer) so
// agg1b can still read d_g. Scan: register double-buffer prefetch.
// ---------------------------------------------------------------------------

#define N_NODES 40000
#define C_FEAT  128
#define N_EDGES 640000
#define SPLIT   20032              // 313 * 64
#define SA_BLK  313                // rows [0, SPLIT)
#define SB_BLK  312                // rows [SPLIT, N_NODES)

__device__ uint32_t d_g [(size_t)N_NODES * C_FEAT / 2];  // layer-1 bf16x2
__device__ uint32_t d_g2[(size_t)N_NODES * C_FEAT / 2];  // layer-2 bf16x2
__device__ float    d_y[(size_t)N_NODES * C_FEAT];       // fp32
__device__ int      d_cnt[N_NODES];    // zero-init; scan re-zeroes after use
__device__ int      d_off[N_NODES + 1];
__device__ int      d_cursor[N_NODES];
__device__ int      d_adj[N_EDGES];
__device__ float    d_dinv[N_NODES];

// ---------------------------------------------------------------------------
__global__ void hist_kernel(const int* __restrict__ ei, int E) {
    int i = blockIdx.x * blockDim.x + threadIdx.x;
    if (i * 4 < E) {
        int4 v = *(const int4*)&ei[E + i * 4];
        atomicAdd(&d_cnt[v.x], 1);
        atomicAdd(&d_cnt[v.y], 1);
        atomicAdd(&d_cnt[v.z], 1);
        atomicAdd(&d_cnt[v.w], 1);
    }
}

// Single 1024-thread block; 40 coalesced tiles, register carry.
// Tile t+1's counts are prefetched into registers before tile t's scan so the
// DRAM latency of each tile load overlaps the previous tile's bar-synced work.
__global__ void scan_kernel() {
    __shared__ int wred[33];
    const int NT = (N_NODES + 1023) / 1024;   // 40 tiles
    int tid = threadIdx.x, lane = tid & 31, wid = tid >> 5;
    int carry = 0;

    int c = d_cnt[tid];                       // tile 0 (tid < 1024 <= N)
    for (int t = 0; t < NT; t++) {
        int inext = (t + 1) * 1024 + tid;
        int cn = 0;
        if (t + 1 < NT && inext < N_NODES) cn = d_cnt[inext];   // prefetch

        int v = c;
#pragma unroll
        for (int d = 1; d < 32; d <<= 1) {
            int u = __shfl_up_sync(0xffffffffu, v, d);
            if (lane >= d) v += u;
        }
        __syncthreads();
        if (lane == 31) wred[wid] = v;
        __syncthreads();
        if (wid == 0) {
            int wv = wred[lane];
            int iv = wv;
#pragma unroll
            for (int d = 1; d < 32; d <<= 1) {
                int u = __shfl_up_sync(0xffffffffu, iv, d);
                if (lane >= d) iv += u;
            }
            wred[lane] = iv - wv;
            if (lane == 31) wred[32] = iv;
        }
        __syncthreads();
        int i = t * 1024 + tid;
        int pos = carry + wred[wid] + (v - c);
        if (i < N_NODES) {
            d_off[i] = pos;
            d_cursor[i] = pos;
            d_dinv[i] = rsqrtf((float)(c + 1));
            d_cnt[i] = 0;                 // restore invariant for next replay
        }
        carry += wred[32];
        c = cn;
    }
    if (tid == 0) d_off[N_NODES] = carry;
}

__global__ void scatter_kernel(const int* __restrict__ ei, int E) {
    int i = blockIdx.x * blockDim.x + threadIdx.x;
    if (i * 4 < E) {
        int4 r = *(const int4*)&ei[i * 4];       // sources
        int4 c = *(const int4*)&ei[E + i * 4];   // targets
        d_adj[atomicAdd(&d_cursor[c.x], 1)] = r.x;
        d_adj[atomicAdd(&d_cursor[c.y], 1)] = r.y;
        d_adj[atomicAdd(&d_cursor[c.z], 1)] = r.z;
        d_adj[atomicAdd(&d_cursor[c.w], 1)] = r.w;
    }
}

// ---------------------------------------------------------------------------
// bf16 pack/unpack helpers (ALU-only unpack).
// ---------------------------------------------------------------------------
__device__ __forceinline__ uint32_t pack_bf2(float lo, float hi) {
    uint32_t r;
    asm("cvt.rn.bf16x2.f32 %0, %1, %2;" : "=r"(r) : "f"(hi), "f"(lo));
    return r;
}

__device__ __forceinline__ void accb(float4& a, uint2 v) {
    a.x += __uint_as_float(v.x << 16);
    a.y += __uint_as_float(v.x & 0xFFFF0000u);
    a.z += __uint_as_float(v.y << 16);
    a.w += __uint_as_float(v.y & 0xFFFF0000u);
}

// ---------------------------------------------------------------------------
// tf32 tensor-core GEMM, cp.async 2-stage pipeline.
// C = A[rows,128] @ B[128,BN].  CTA: 64 x BN, 8 warps (2x4), warp 32 x BN/4.
// a_sel: 0=Aext 1=d_y.  c_sel: 0=fp32 Cext, 1=bf16 d_g, 2=bf16 d_g2.
// row_base: first row of this launch's tile range (split pipelining).
// ---------------------------------------------------------------------------
__device__ __forceinline__ uint32_t f2tf(float f) {
    uint32_t r;
    asm("cvt.rna.tf32.f32 %0, %1;" : "=r"(r) : "f"(f));
    return r;
}

__device__ __forceinline__ void cp16(uint32_t saddr, const void* gptr) {
    asm volatile("cp.async.ca.shared.global [%0], [%1], 16;\n"
                 :: "r"(saddr), "l"(gptr));
}

template <int BN>
__global__ void __launch_bounds__(256, 3)
gemm_tf32_kernel(const float* __restrict__ Aext,
                 const float* __restrict__ B,
                 const float* __restrict__ bias,
                 float* __restrict__ Cext,
                 int a_sel, int c_sel, int use_rowscale, int row_base) {
    constexpr int BM = 64, KC = 16, NKC = C_FEAT / KC;   // 8 chunks
    constexpr int AP = 20;
    constexpr int NP = BN + 8;
    constexpr int WN = BN / 4;
    constexpr int MF = 2;
    constexpr int NF = WN / 8;
    constexpr int BV = KC * BN / 4;

    __shared__ float As[2][BM * AP];
    __shared__ float Bs[2][KC * NP];

    const float* A = (a_sel == 0) ? Aext : (const float*)d_y;

    int tid = threadIdx.x;
    int lane = tid & 31;
    int wid = tid >> 5;
    int warp_m = wid & 1;
    int warp_n = wid >> 1;
    int qid = lane >> 2;
    int qt = lane & 3;
    int row0 = row_base + blockIdx.x * BM;

    uint32_t a_smem[2], b_smem[2];
#pragma unroll
    for (int s = 0; s < 2; s++) {
        a_smem[s] = (uint32_t)__cvta_generic_to_shared(&As[s][0]);
        b_smem[s] = (uint32_t)__cvta_generic_to_shared(&Bs[s][0]);
    }

    auto load_chunk = [&](int kc, int st) {
        int k0 = kc * KC;
        {
            int r = tid >> 2, vv = tid & 3;
            int gr = row0 + r; if (gr >= N_NODES) gr = N_NODES - 1;
            cp16(a_smem[st] + (r * AP + vv * 4) * 4,
                 &A[(size_t)gr * C_FEAT + k0 + vv * 4]);
        }
#pragma unroll
        for (int i = 0; i < BV / 256; i++) {
            int idx = tid + i * 256;
            int r = idx / (BN / 4), vv = idx % (BN / 4);
            cp16(b_smem[st] + (r * NP + vv * 4) * 4,
                 &B[(size_t)(k0 + r) * BN + vv * 4]);
        }
        asm volatile("cp.async.commit_group;" ::: "memory");
    };

    float acc[MF][NF][4];
#pragma unroll
    for (int i = 0; i < MF; i++)
#pragma unroll
        for (int j = 0; j < NF; j++)
#pragma unroll
            for (int k = 0; k < 4; k++) acc[i][j][k] = 0.f;

    load_chunk(0, 0);

    for (int kc = 0; kc < NKC; kc++) {
        int st = kc & 1;
        if (kc + 1 < NKC) {
            load_chunk(kc + 1, st ^ 1);
            asm volatile("cp.async.wait_group 1;" ::: "memory");
        } else {
            asm volatile("cp.async.wait_group 0;" ::: "memory");
        }
        __syncthreads();

        const float* __restrict__ Asb = As[st];
        const float* __restrict__ Bsb = Bs[st];
#pragma unroll
        for (int k8 = 0; k8 < KC / 8; k8++) {
            int kb = k8 * 8;
            uint32_t af[MF][4];
#pragma unroll
            for (int im = 0; im < MF; im++) {
                int m0 = warp_m * 32 + im * 16 + qid;
                af[im][0] = f2tf(Asb[m0 * AP + kb + qt]);
                af[im][1] = f2tf(Asb[(m0 + 8) * AP + kb + qt]);
                af[im][2] = f2tf(Asb[m0 * AP + kb + qt + 4]);
                af[im][3] = f2tf(Asb[(m0 + 8) * AP + kb + qt + 4]);
            }
            uint32_t bf[NF][2];
#pragma unroll
            for (int jn = 0; jn < NF; jn++) {
                int n0 = warp_n * WN + jn * 8 + qid;
                bf[jn][0] = f2tf(Bsb[(kb + qt) * NP + n0]);
                bf[jn][1] = f2tf(Bsb[(kb + qt + 4) * NP + n0]);
            }
#pragma unroll
            for (int im = 0; im < MF; im++)
#pragma unroll
                for (int jn = 0; jn < NF; jn++) {
                    asm volatile(
                        "mma.sync.aligned.m16n8k8.row.col.f32.tf32.tf32.f32 "
                        "{%0,%1,%2,%3}, {%4,%5,%6,%7}, {%8,%9}, {%0,%1,%2,%3};\n"
                        : "+f"(acc[im][jn][0]), "+f"(acc[im][jn][1]),
                          "+f"(acc[im][jn][2]), "+f"(acc[im][jn][3])
                        : "r"(af[im][0]), "r"(af[im][1]), "r"(af[im][2]), "r"(af[im][3]),
                          "r"(bf[jn][0]), "r"(bf[jn][1]));
                }
        }
        __syncthreads();
    }

    uint32_t* Cb = (c_sel == 1) ? d_g : d_g2;
#pragma unroll
    for (int im = 0; im < MF; im++) {
        int ra = row0 + warp_m * 32 + im * 16 + qid;
        int rb = ra + 8;
        float sa = 1.f, sb = 1.f;
        if (use_rowscale) {
            if (ra < N_NODES) sa = d_dinv[ra];
            if (rb < N_NODES) sb = d_dinv[rb];
        }
#pragma unroll
        for (int jn = 0; jn < NF; jn++) {
            int col = warp_n * WN + jn * 8 + qt * 2;
            float bx = 0.f, by = 0.f;
            if (bias) { bx = bias[col]; by = bias[col + 1]; }
            float oax = fmaf(acc[im][jn][0], sa, bx), oay = fmaf(acc[im][jn][1], sa, by);
            float obx = fmaf(acc[im][jn][2], sb, bx), oby = fmaf(acc[im][jn][3], sb, by);
            if (c_sel) {
                if (ra < N_NODES)
                    Cb[(size_t)ra * (C_FEAT / 2) + (col >> 1)] = pack_bf2(oax, oay);
                if (rb < N_NODES)
                    Cb[(size_t)rb * (C_FEAT / 2) + (col >> 1)] = pack_bf2(obx, oby);
            } else {
                if (ra < N_NODES)
                    *(float2*)&Cext[(size_t)ra * BN + col] = make_float2(oax, oay);
                if (rb < N_NODES)
                    *(float2*)&Cext[(size_t)rb * BN + col] = make_float2(obx, oby);
            }
        }
    }
}

// ---------------------------------------------------------------------------
// Aggregation: one warp per node, bf16x2 gathers, fp32 accumulate.
// g_sel picks layer buffer; [node_base, node_end) for split pipelining.
// ---------------------------------------------------------------------------
__global__ void agg_kernel(const float* __restrict__ bias, int g_sel,
                           int node_base, int node_end) {
    int gw = node_base + ((blockIdx.x * blockDim.x + threadIdx.x) >> 5);
    if (gw >= node_end) return;
    int lane = threadIdx.x & 31;
    int cw = lane << 1;
    const uint32_t* __restrict__ g = (g_sel == 1) ? d_g : d_g2;

    float4 a0 = make_float4(0.f, 0.f, 0.f, 0.f);
    float4 a1 = a0, a2 = a0, a3 = a0;
    accb(a0, *(const uint2*)&g[(size_t)gw * (C_FEAT / 2) + cw]);  // self loop

    int s = d_off[gw], e = d_off[gw + 1];
    for (int base = s; base < e; base += 32) {
        int m = e - base; if (m > 32) m = 32;
        int myu = (lane < m) ? d_adj[base + lane] : 0;
        int j = 0;
        for (; j + 4 <= m; j += 4) {
            int u0 = __shfl_sync(0xffffffffu, myu, j);
            int u1 = __shfl_sync(0xffffffffu, myu, j + 1);
            int u2 = __shfl_sync(0xffffffffu, myu, j + 2);
            int u3 = __shfl_sync(0xffffffffu, myu, j + 3);
            uint2 t0 = *(const uint2*)&g[(size_t)u0 * (C_FEAT / 2) + cw];
            uint2 t1 = *(const uint2*)&g[(size_t)u1 * (C_FEAT / 2) + cw];
            uint2 t2 = *(const uint2*)&g[(size_t)u2 * (C_FEAT / 2) + cw];
            uint2 t3 = *(const uint2*)&g[(size_t)u3 * (C_FEAT / 2) + cw];
            accb(a0, t0); accb(a1, t1); accb(a2, t2); accb(a3, t3);
        }
        for (; j < m; j++) {
            int u = __shfl_sync(0xffffffffu, myu, j);
            accb(a0, *(const uint2*)&g[(size_t)u * (C_FEAT / 2) + cw]);
        }
    }
    float4 acc = make_float4(a0.x + a1.x + a2.x + a3.x,
                             a0.y + a1.y + a2.y + a3.y,
                             a0.z + a1.z + a2.z + a3.z,
                             a0.w + a1.w + a2.w + a3.w);
    int c = lane << 2;
    float dv = d_dinv[gw];
    float4 bb = *(const float4*)&bias[c];
    float4 o;
    o.x = fmaxf(fmaf(acc.x, dv, bb.x), 0.f);
    o.y = fmaxf(fmaf(acc.y, dv, bb.y), 0.f);
    o.z = fmaxf(fmaf(acc.z, dv, bb.z), 0.f);
    o.w = fmaxf(fmaf(acc.w, dv, bb.w), 0.f);
    *(float4*)&d_y[(size_t)gw * C_FEAT + c] = o;
}

// ---------------------------------------------------------------------------
extern "C" void kernel_launch(void* const* d_in, const int* in_sizes, int n_in,
                              void* d_out, int out_size) {
    const float* x  = (const float*)d_in[0];
    const int*   ei = (const int*)d_in[1];     // int32
    const float* W1 = (const float*)d_in[2];
    const float* b1 = (const float*)d_in[3];
    const float* W2 = (const float*)d_in[4];
    const float* b2 = (const float*)d_in[5];
    const float* Wl = (const float*)d_in[6];
    const float* bl = (const float*)d_in[7];
    float* out = (float*)d_out;

    int E = in_sizes[1] / 2;   // 640000

    static cudaStream_t s2 = []() {
        cudaStream_t s; cudaStreamCreateWithFlags(&s, cudaStreamNonBlocking); return s;
    }();
    static cudaEvent_t ev[6] = {};
    if (!ev[0]) {
        for (int i = 0; i < 6; i++)
            cudaEventCreateWithFlags(&ev[i], cudaEventDisableTiming);
    }

    const int AGG_A = (SPLIT * 32) / 256;                       // 2504 blocks
    const int AGG_B = ((N_NODES - SPLIT) * 32 + 255) / 256;     // 2496 blocks

    // CSR: hist + scan (gemm1 rowscale needs d_dinv).
    hist_kernel<<<(E / 4 + 255) / 256, 256>>>(ei, E);
    scan_kernel<<<1, 1024>>>();

    // Fork 1: gemm1 (x @ W1 -> d_g, all rows) || scatter.
    cudaEventRecord(ev[0], 0);
    cudaStreamWaitEvent(s2, ev[0], 0);
    gemm_tf32_kernel<128><<<SA_BLK + SB_BLK, 256, 0, s2>>>(x, W1, nullptr, nullptr, 0, 1, 1, 0);
    cudaEventRecord(ev[1], s2);
    scatter_kernel<<<(E / 4 + 255) / 256, 256>>>(ei, E);
    cudaStreamWaitEvent(0, ev[1], 0);

    // agg1a (nodes [0,SPLIT)) -> y[0:S]
    agg_kernel<<<AGG_A, 256>>>(b1, 1, 0, SPLIT);

    // Fork 2: gemm2a (rows [0,SPLIT), y -> d_g2) || agg1b (nodes [S,N)).
    cudaEventRecord(ev[2], 0);
    cudaStreamWaitEvent(s2, ev[2], 0);
    gemm_tf32_kernel<128><<<SA_BLK, 256, 0, s2>>>(nullptr, W2, nullptr, nullptr, 1, 2, 1, 0);
    cudaEventRecord(ev[3], s2);
    agg_kernel<<<AGG_B, 256>>>(b1, 1, SPLIT, N_NODES);
    cudaStreamWaitEvent(0, ev[3], 0);

    // gemm2b (rows [SPLIT,N)) — after agg1b (y[S:N]) and join of gemm2a.
    gemm_tf32_kernel<128><<<SB_BLK, 256>>>(nullptr, W2, nullptr, nullptr, 1, 2, 1, SPLIT);

    // agg2a (nodes [0,SPLIT), gathers all of d_g2) -> y[0:S]
    agg_kernel<<<AGG_A, 256>>>(b2, 2, 0, SPLIT);

    // Fork 3: head_a (rows [0,SPLIT)) || agg2b (nodes [S,N)).
    cudaEventRecord(ev[4], 0);
    cudaStreamWaitEvent(s2, ev[4], 0);
    gemm_tf32_kernel<64><<<SA_BLK, 256, 0, s2>>>(nullptr, Wl, bl, out, 1, 0, 0, 0);
    cudaEventRecord(ev[5], s2);
    agg_kernel<<<AGG_B, 256>>>(b2, 2, SPLIT, N_NODES);
    cudaStreamWaitEvent(0, ev[5], 0);

    // head_b (rows [SPLIT,N)).
    gemm_tf32_kernel<64><<<SB_BLK, 256>>>(nullptr, Wl, bl, out, 1, 0, 0, SPLIT);
}